// round 2
// baseline (speedup 1.0000x reference)
#include <cuda_runtime.h>
#include <cuda_bf16.h>
#include <math.h>

// ---------------------------------------------------------------------------
// NonLocal block, B=16, C=256, IC=128, H=W=64.
// View quirk: [b,128,4096] <-> [b,256,2048] is a linear reinterpret, so all
// reshapes/transposes in the reference are handled purely by strides here.
//
// Pipeline (all fp32, SIMT SGEMM this round):
//   1) phi/theta/g = W[128x256] @ x[b][256x4096] + bias      (fused 1 launch)
//   2) attnT[b][m][n] = sum_c PHI_v[c][m] * THETA_v[c][n]    (TN GEMM 2048x2048x256)
//   3) row softmax over n of attnT  (== reference softmax over axis=1)
//   4) OUT_v[b][c][n] = sum_m G_v[c][m] * attnT[m][n]        (NN GEMM 256x2048x2048)
//   5) mask = w_mask[256x128] @ OUT[b][128x4096] + b_mask + x
// ---------------------------------------------------------------------------

#define BATCH 16
#define CH    256
#define ICH   128
#define HW    4096
#define NV    2048   // viewed sequence length
#define CV    256    // viewed channels

// Scratch (device globals; allocation-free per harness rules)
// proj layout: [3][BATCH][ICH][HW]  (0=phi, 1=theta, 2=g)
__device__ __align__(16) float g_proj [(size_t)3 * BATCH * ICH * HW];    // 96 MB
__device__ __align__(16) float g_attn [(size_t)BATCH * NV * NV];         // 256 MB
__device__ __align__(16) float g_out  [(size_t)BATCH * ICH * HW];        // 32 MB

// ---------------------------------------------------------------------------
// Generic batched SGEMM:  C[b] = op(A[b]) @ B[b] (+ bias) (+ res)
//   ATRANS=false: A is [M,K] row-major (lda=K)
//   ATRANS=true : A is [K,M] row-major (lda=M)
//   B is always [K,N] row-major (ldb=N). C is [M,N] row-major.
// ---------------------------------------------------------------------------
#define BM 128
#define BN 128
#define BK 16
#define TM 8
#define TN 8
#define PAD 4

template<bool ATRANS, bool BIAS, bool RES>
__global__ __launch_bounds__(256, 2)
void sgemm_kernel(const float* __restrict__ A, const float* __restrict__ B,
                  const float* __restrict__ bias, const float* __restrict__ res,
                  float* __restrict__ C,
                  int M, int N, int K,
                  size_t sA, size_t sB, size_t sC)
{
    const int bz = blockIdx.z;
    const float* Ap = A + (size_t)bz * sA;
    const float* Bp = B + (size_t)bz * sB;
    float*       Cp = C + (size_t)bz * sC;
    const float* Rp = RES ? (res + (size_t)bz * sC) : nullptr;

    const int m0 = blockIdx.y * BM;
    const int n0 = blockIdx.x * BN;

    __shared__ float As[BK][BM + PAD];
    __shared__ float Bs[BK][BN + PAD];

    const int tid = threadIdx.x;
    const int tx  = tid & 15;   // column group
    const int ty  = tid >> 4;   // row group

    float acc[TM][TN];
#pragma unroll
    for (int i = 0; i < TM; i++)
#pragma unroll
        for (int j = 0; j < TN; j++) acc[i][j] = 0.f;

    for (int k0 = 0; k0 < K; k0 += BK) {
        // ---- load A tile into As[k][m] ----
        if (ATRANS) {
#pragma unroll
            for (int i = 0; i < 2; i++) {
                int v  = tid + i * 256;       // 0..511 float4 slots
                int k  = v >> 5;              // /32 (BM/4 float4 per row)
                int m4 = (v & 31) << 2;
                float4 f = *reinterpret_cast<const float4*>(
                    &Ap[(size_t)(k0 + k) * M + m0 + m4]);
                *reinterpret_cast<float4*>(&As[k][m4]) = f;
            }
        } else {
#pragma unroll
            for (int i = 0; i < 2; i++) {
                int v  = tid + i * 256;
                int m  = v >> 2;              // /4 (BK/4 float4 per row)
                int k4 = (v & 3) << 2;
                float4 f = *reinterpret_cast<const float4*>(
                    &Ap[(size_t)(m0 + m) * K + k0 + k4]);
                As[k4 + 0][m] = f.x;
                As[k4 + 1][m] = f.y;
                As[k4 + 2][m] = f.z;
                As[k4 + 3][m] = f.w;
            }
        }
        // ---- load B tile into Bs[k][n] ----
#pragma unroll
        for (int i = 0; i < 2; i++) {
            int v  = tid + i * 256;
            int k  = v >> 5;
            int n4 = (v & 31) << 2;
            float4 f = *reinterpret_cast<const float4*>(
                &Bp[(size_t)(k0 + k) * N + n0 + n4]);
            *reinterpret_cast<float4*>(&Bs[k][n4]) = f;
        }
        __syncthreads();

#pragma unroll
        for (int k = 0; k < BK; k++) {
            float a[TM], bb[TN];
#pragma unroll
            for (int i = 0; i < TM; i++) a[i] = As[k][ty * TM + i];
#pragma unroll
            for (int j = 0; j < TN; j++) bb[j] = Bs[k][tx * TN + j];
#pragma unroll
            for (int i = 0; i < TM; i++)
#pragma unroll
                for (int j = 0; j < TN; j++)
                    acc[i][j] = fmaf(a[i], bb[j], acc[i][j]);
        }
        __syncthreads();
    }

    // ---- epilogue ----
#pragma unroll
    for (int i = 0; i < TM; i++) {
        int m = m0 + ty * TM + i;
        float bv = BIAS ? bias[m] : 0.f;
        size_t base = (size_t)m * N + n0 + tx * TN;
#pragma unroll
        for (int j4 = 0; j4 < TN; j4 += 4) {
            float4 o;
            o.x = acc[i][j4 + 0] + bv;
            o.y = acc[i][j4 + 1] + bv;
            o.z = acc[i][j4 + 2] + bv;
            o.w = acc[i][j4 + 3] + bv;
            if (RES) {
                float4 r = *reinterpret_cast<const float4*>(&Rp[base + j4]);
                o.x += r.x; o.y += r.y; o.z += r.z; o.w += r.w;
            }
            *reinterpret_cast<float4*>(&Cp[base + j4]) = o;
        }
    }
}

// ---------------------------------------------------------------------------
// Fused projection GEMM: one launch computes phi, theta, g.
// blockIdx.z = w * BATCH + b, w in {0,1,2} selects weight/bias/output.
// C[w][b] = W_w[128x256] @ x[b][256x4096] + bias_w
// ---------------------------------------------------------------------------
__global__ __launch_bounds__(256, 2)
void proj_kernel(const float* __restrict__ X,
                 const float* __restrict__ w_phi,   const float* __restrict__ b_phi,
                 const float* __restrict__ w_theta, const float* __restrict__ b_theta,
                 const float* __restrict__ w_g,     const float* __restrict__ b_g,
                 float* __restrict__ proj)
{
    const int which = blockIdx.z / BATCH;
    const int bz    = blockIdx.z % BATCH;
    const float* Ap   = (which == 0) ? w_phi : (which == 1) ? w_theta : w_g;
    const float* bias = (which == 0) ? b_phi : (which == 1) ? b_theta : b_g;
    const float* Bp = X + (size_t)bz * CH * HW;
    float* Cp = proj + ((size_t)which * BATCH + bz) * ICH * HW;

    const int M = ICH, N = HW, K = CH;
    const int m0 = blockIdx.y * BM;
    const int n0 = blockIdx.x * BN;

    __shared__ float As[BK][BM + PAD];
    __shared__ float Bs[BK][BN + PAD];

    const int tid = threadIdx.x;
    const int tx  = tid & 15;
    const int ty  = tid >> 4;

    float acc[TM][TN];
#pragma unroll
    for (int i = 0; i < TM; i++)
#pragma unroll
        for (int j = 0; j < TN; j++) acc[i][j] = 0.f;

    for (int k0 = 0; k0 < K; k0 += BK) {
#pragma unroll
        for (int i = 0; i < 2; i++) {
            int v  = tid + i * 256;
            int m  = v >> 2;
            int k4 = (v & 3) << 2;
            float4 f = *reinterpret_cast<const float4*>(
                &Ap[(size_t)(m0 + m) * K + k0 + k4]);
            As[k4 + 0][m] = f.x;
            As[k4 + 1][m] = f.y;
            As[k4 + 2][m] = f.z;
            As[k4 + 3][m] = f.w;
        }
#pragma unroll
        for (int i = 0; i < 2; i++) {
            int v  = tid + i * 256;
            int k  = v >> 5;
            int n4 = (v & 31) << 2;
            float4 f = *reinterpret_cast<const float4*>(
                &Bp[(size_t)(k0 + k) * N + n0 + n4]);
            *reinterpret_cast<float4*>(&Bs[k][n4]) = f;
        }
        __syncthreads();

#pragma unroll
        for (int k = 0; k < BK; k++) {
            float a[TM], bb[TN];
#pragma unroll
            for (int i = 0; i < TM; i++) a[i] = As[k][ty * TM + i];
#pragma unroll
            for (int j = 0; j < TN; j++) bb[j] = Bs[k][tx * TN + j];
#pragma unroll
            for (int i = 0; i < TM; i++)
#pragma unroll
                for (int j = 0; j < TN; j++)
                    acc[i][j] = fmaf(a[i], bb[j], acc[i][j]);
        }
        __syncthreads();
    }

#pragma unroll
    for (int i = 0; i < TM; i++) {
        int m = m0 + ty * TM + i;
        float bv = bias[m];
        size_t base = (size_t)m * N + n0 + tx * TN;
#pragma unroll
        for (int j4 = 0; j4 < TN; j4 += 4) {
            float4 o;
            o.x = acc[i][j4 + 0] + bv;
            o.y = acc[i][j4 + 1] + bv;
            o.z = acc[i][j4 + 2] + bv;
            o.w = acc[i][j4 + 3] + bv;
            *reinterpret_cast<float4*>(&Cp[base + j4]) = o;
        }
    }
}

// ---------------------------------------------------------------------------
// Row softmax over contiguous rows of length NV (=2048). One block per row.
// ---------------------------------------------------------------------------
__global__ __launch_bounds__(256)
void softmax_kernel(float* __restrict__ attn)
{
    float* p = attn + (size_t)blockIdx.x * NV;
    const int tid  = threadIdx.x;
    const int lane = tid & 31;
    const int warp = tid >> 5;

    float4 a = *reinterpret_cast<const float4*>(p + tid * 8);
    float4 b = *reinterpret_cast<const float4*>(p + tid * 8 + 4);
    float v[8] = {a.x, a.y, a.z, a.w, b.x, b.y, b.z, b.w};

    float m = v[0];
#pragma unroll
    for (int i = 1; i < 8; i++) m = fmaxf(m, v[i]);
#pragma unroll
    for (int o = 16; o > 0; o >>= 1)
        m = fmaxf(m, __shfl_xor_sync(0xffffffffu, m, o));

    __shared__ float smax[8];
    __shared__ float ssum[8];
    if (lane == 0) smax[warp] = m;
    __syncthreads();
    m = smax[0];
#pragma unroll
    for (int i = 1; i < 8; i++) m = fmaxf(m, smax[i]);

    float s = 0.f;
#pragma unroll
    for (int i = 0; i < 8; i++) { v[i] = expf(v[i] - m); s += v[i]; }
#pragma unroll
    for (int o = 16; o > 0; o >>= 1)
        s += __shfl_xor_sync(0xffffffffu, s, o);
    if (lane == 0) ssum[warp] = s;
    __syncthreads();
    s = ssum[0];
#pragma unroll
    for (int i = 1; i < 8; i++) s += ssum[i];

    float inv = 1.f / s;
    float4 o1 = make_float4(v[0] * inv, v[1] * inv, v[2] * inv, v[3] * inv);
    float4 o2 = make_float4(v[4] * inv, v[5] * inv, v[6] * inv, v[7] * inv);
    *reinterpret_cast<float4*>(p + tid * 8)     = o1;
    *reinterpret_cast<float4*>(p + tid * 8 + 4) = o2;
}

// ---------------------------------------------------------------------------
extern "C" void kernel_launch(void* const* d_in, const int* in_sizes, int n_in,
                              void* d_out, int out_size)
{
    const float* x       = (const float*)d_in[0];
    const float* w_phi   = (const float*)d_in[1];
    const float* b_phi   = (const float*)d_in[2];
    const float* w_theta = (const float*)d_in[3];
    const float* b_theta = (const float*)d_in[4];
    const float* w_g     = (const float*)d_in[5];
    const float* b_g     = (const float*)d_in[6];
    const float* w_mask  = (const float*)d_in[7];
    const float* b_mask  = (const float*)d_in[8];
    float*       out     = (float*)d_out;

    static float* proj = nullptr;
    static float* attn = nullptr;
    static float* obuf = nullptr;
    if (proj == nullptr) {
        cudaGetSymbolAddress((void**)&proj, g_proj);
        cudaGetSymbolAddress((void**)&attn, g_attn);
        cudaGetSymbolAddress((void**)&obuf, g_out);
    }
    float* phi   = proj;
    float* theta = proj + (size_t)1 * BATCH * ICH * HW;
    float* gg    = proj + (size_t)2 * BATCH * ICH * HW;

    const size_t sX    = (size_t)CH * HW;    // 256*4096 per batch
    const size_t sProj = (size_t)ICH * HW;   // 128*4096 per batch (== CV*NV)
    const size_t sAttn = (size_t)NV * NV;    // 2048*2048 per batch

    // 1) fused projections: 3 weights x 16 batches in one launch
    {
        dim3 grid(HW / BN, ICH / BM, 3 * BATCH);
        proj_kernel<<<grid, 256>>>(x, w_phi, b_phi, w_theta, b_theta,
                                   w_g, b_g, proj);
    }

    // 2) attnT[b][m][n] = sum_c PHI_v[c][m] * THETA_v[c][n]
    //    A = PHI_v [K=256, M=2048] (ATRANS), B = THETA_v [K=256, N=2048]
    {
        dim3 grid(NV / BN, NV / BM, BATCH);
        sgemm_kernel<true, false, false><<<grid, 256>>>(
            phi, theta, nullptr, nullptr, attn, NV, NV, CV, sProj, sProj, sAttn);
    }

    // 3) softmax over contiguous n (reference axis=1)
    softmax_kernel<<<BATCH * NV, 256>>>(attn);

    // 4) OUT_v[b][c][n] = sum_m G_v[c][m] * attnT[m][n]
    //    A = G_v [M=256, K=2048], B = attnT [K=2048, N=2048]
    {
        dim3 grid(NV / BN, CV / BM, BATCH);
        sgemm_kernel<false, false, false><<<grid, 256>>>(
            gg, attn, nullptr, nullptr, obuf, CV, NV, NV, sProj, sAttn, sProj);
    }

    // 5) mask = w_mask @ OUT + b_mask + x  (M=256, N=4096, K=128)
    {
        dim3 grid(HW / BN, CH / BM, BATCH);
        sgemm_kernel<false, true, true><<<grid, 256>>>(
            w_mask, obuf, b_mask, x, out, CH, HW, ICH, 0, sProj, sX);
    }
}

// round 4
// speedup vs baseline: 1.7763x; 1.7763x over previous
#include <cuda_runtime.h>
#include <cuda_bf16.h>
#include <math.h>
#include <stdint.h>

// ---------------------------------------------------------------------------
// NonLocal block, B=16, C=256, IC=128, H=W=64.  Tensor-core via mma.sync
// (sm_100 base target: tcgen05 is not available on this toolchain config).
//   1) proj (SIMT fp32):  phi/theta/g = W @ x + b
//   2) convQK: phi,theta -> [m][k] bf16 hi/lo (K-major, transposed)
//      convG : g -> bf16 hi/lo (already K-major)
//   3) GEMM2 (mma.sync bf16 split-3): attnT[m][n] = phi_v^T @ theta_v (f32)
//   4) stats: row max + 1/sumexp per (b,m)
//   5) normT: attn -> softmaxed, transposed, bf16 hi/lo  [n][m]
//   6) GEMM4 (mma.sync bf16 split-3): OUT_v[c][n] = g_v @ P
//   7) mask (SIMT fp32): w_mask @ OUT + b_mask + x
// ---------------------------------------------------------------------------

#define BATCH 16
#define CH    256
#define ICH   128
#define HW    4096
#define NV    2048
#define CV    256

// ------------------------------- scratch ----------------------------------
__device__ __align__(16) float g_proj [(size_t)3 * BATCH * ICH * HW];      // 96 MB
__device__ __align__(16) float g_attn [(size_t)BATCH * NV * NV];           // 256 MB
__device__ __align__(16) float g_out  [(size_t)BATCH * ICH * HW];          // 32 MB
__device__ __align__(16) __nv_bfloat16 g_qkT_hi[(size_t)2 * BATCH * NV * CV]; // 32 MB
__device__ __align__(16) __nv_bfloat16 g_qkT_lo[(size_t)2 * BATCH * NV * CV]; // 32 MB
__device__ __align__(16) __nv_bfloat16 g_g_hi [(size_t)BATCH * CV * NV];   // 16 MB
__device__ __align__(16) __nv_bfloat16 g_g_lo [(size_t)BATCH * CV * NV];   // 16 MB
__device__ __align__(16) __nv_bfloat16 g_at_hi[(size_t)BATCH * NV * NV];   // 128 MB
__device__ __align__(16) __nv_bfloat16 g_at_lo[(size_t)BATCH * NV * NV];   // 128 MB
__device__ __align__(16) float2 g_stats[(size_t)BATCH * NV];

// --------------------------- helpers ---------------------------------------
__device__ __forceinline__ uint32_t smem_u32(const void* p) {
    uint32_t a;
    asm("{ .reg .u64 t; cvta.to.shared.u64 t, %1; cvt.u32.u64 %0, t; }"
        : "=r"(a) : "l"(p));
    return a;
}
__device__ __forceinline__ void ldsm4(uint32_t* r, uint32_t a) {
    asm volatile("ldmatrix.sync.aligned.m8n8.x4.shared.b16 {%0,%1,%2,%3}, [%4];"
                 : "=r"(r[0]), "=r"(r[1]), "=r"(r[2]), "=r"(r[3]) : "r"(a));
}
__device__ __forceinline__ void mma16816(float* d, const uint32_t* a, const uint32_t* b) {
    asm volatile(
        "mma.sync.aligned.m16n8k16.row.col.f32.bf16.bf16.f32 "
        "{%0,%1,%2,%3}, {%4,%5,%6,%7}, {%8,%9}, {%0,%1,%2,%3};"
        : "+f"(d[0]), "+f"(d[1]), "+f"(d[2]), "+f"(d[3])
        : "r"(a[0]), "r"(a[1]), "r"(a[2]), "r"(a[3]), "r"(b[0]), "r"(b[1]));
}
__device__ __forceinline__ void cp16(uint32_t dst, const void* src) {
    asm volatile("cp.async.cg.shared.global [%0], [%1], 16;" :: "r"(dst), "l"(src));
}

// ---------------------------------------------------------------------------
// Split-bf16 TN GEMM via mma.sync:
//   C[bz][m][n] = sum_k (Ahi+Alo)[m][k]*(Bhi+Blo)[n][k]   (hi*hi+hi*lo+lo*hi)
// A,B K-major bf16 (ld=K), C f32 row-major (ld=N).
// CTA tile 128x128x64, 8 warps (64x32 each), 3-stage cp.async pipeline.
// ---------------------------------------------------------------------------
#define MM_BK     64
#define MM_STAGES 3
#define TILE16K   16384          // 128 rows * 128 B
#define STG_BYTES (4 * TILE16K)  // Ahi, Alo, Bhi, Blo
#define MM_SMEM   (MM_STAGES * STG_BYTES)

__global__ __launch_bounds__(256, 1)
void mma_gemm(const __nv_bfloat16* __restrict__ Ahi, const __nv_bfloat16* __restrict__ Alo,
              const __nv_bfloat16* __restrict__ Bhi, const __nv_bfloat16* __restrict__ Blo,
              float* __restrict__ C,
              int M, int N, int K, size_t sA, size_t sB, size_t sC)
{
    extern __shared__ __align__(1024) char smem[];
    const int tid  = threadIdx.x;
    const int wid  = tid >> 5;
    const int lane = tid & 31;
    const int bz = blockIdx.z;
    const int m0 = blockIdx.y * 128;
    const int n0 = blockIdx.x * 128;
    const int warp_m = (wid >> 2) * 64;   // 0 or 64
    const int warp_n = (wid & 3) * 32;    // 0,32,64,96

    const __nv_bfloat16* tp[4];
    tp[0] = Ahi + (size_t)bz * sA + (size_t)m0 * K;
    tp[1] = Alo + (size_t)bz * sA + (size_t)m0 * K;
    tp[2] = Bhi + (size_t)bz * sB + (size_t)n0 * K;
    tp[3] = Blo + (size_t)bz * sB + (size_t)n0 * K;

    const uint32_t sbase = smem_u32(smem);
    const int nk = K / MM_BK;

    // ---- async stage loader: 4096 16B chunks per stage, 16 per thread ----
    auto load_stage = [&](int it) {
        const int k0 = it * MM_BK;
        const uint32_t sdst = sbase + (uint32_t)(it % MM_STAGES) * STG_BYTES;
#pragma unroll
        for (int j = 0; j < 16; ++j) {
            int idx  = j * 256 + tid;
            int tile = idx >> 10;
            int row  = (idx >> 3) & 127;
            int ck   = idx & 7;
            const __nv_bfloat16* src = tp[tile] + (size_t)row * K + k0 + ck * 8;
            uint32_t dst = sdst + (uint32_t)tile * TILE16K + row * 128 +
                           (((uint32_t)(ck ^ (row & 7))) << 4);
            cp16(dst, src);
        }
        asm volatile("cp.async.commit_group;" ::: "memory");
    };

    float acc[4][4][4];
#pragma unroll
    for (int mi = 0; mi < 4; ++mi)
#pragma unroll
        for (int ni = 0; ni < 4; ++ni)
#pragma unroll
            for (int q = 0; q < 4; ++q) acc[mi][ni][q] = 0.f;

    const int npre = (MM_STAGES - 1 < nk) ? MM_STAGES - 1 : nk;
    for (int s = 0; s < npre; ++s) load_stage(s);

    // per-thread ldmatrix row indices (canonical sm80 pattern)
    const int a_rl = lane & 15;               // row within 16
    const int a_ck = (lane >> 4);             // 0/1 -> k-chunk offset
    const int b_rl = ((lane >> 4) << 3) + (lane & 7);
    const int b_ck = (lane >> 3) & 1;

    for (int it = 0; it < nk; ++it) {
        if (it + MM_STAGES - 1 < nk) {
            load_stage(it + MM_STAGES - 1);
            asm volatile("cp.async.wait_group %0;" :: "n"(MM_STAGES - 2) : "memory");
        } else {
            asm volatile("cp.async.wait_group 0;" ::: "memory");
        }
        __syncthreads();

        const uint32_t sa = sbase + (uint32_t)(it % MM_STAGES) * STG_BYTES;
        const uint32_t sb = sa + 2 * TILE16K;

#pragma unroll
        for (int ks = 0; ks < 4; ++ks) {
            uint32_t ah[4][4], al[4][4];
            const int achunk = ks * 2 + a_ck;
#pragma unroll
            for (int mi = 0; mi < 4; ++mi) {
                int mrow = warp_m + mi * 16 + a_rl;
                uint32_t ad = sa + mrow * 128 + ((uint32_t)(achunk ^ (mrow & 7)) << 4);
                ldsm4(ah[mi], ad);
                ldsm4(al[mi], ad + TILE16K);
            }
            uint32_t bh[2][4], bl[2][4];
            const int bchunk = ks * 2 + b_ck;
#pragma unroll
            for (int nj = 0; nj < 2; ++nj) {
                int nrow = warp_n + nj * 16 + b_rl;
                uint32_t bd = sb + nrow * 128 + ((uint32_t)(bchunk ^ (nrow & 7)) << 4);
                ldsm4(bh[nj], bd);
                ldsm4(bl[nj], bd + TILE16K);
            }
#pragma unroll
            for (int mi = 0; mi < 4; ++mi)
#pragma unroll
                for (int ni = 0; ni < 4; ++ni) {
                    const uint32_t* ph = &bh[ni >> 1][(ni & 1) * 2];
                    const uint32_t* pl = &bl[ni >> 1][(ni & 1) * 2];
                    mma16816(acc[mi][ni], ah[mi], ph);   // hi*hi
                    mma16816(acc[mi][ni], ah[mi], pl);   // hi*lo
                    mma16816(acc[mi][ni], al[mi], ph);   // lo*hi
                }
        }
        __syncthreads();
    }

    // ---- epilogue: direct f32 stores ----
    float* Cb = C + (size_t)bz * sC;
#pragma unroll
    for (int mi = 0; mi < 4; ++mi) {
#pragma unroll
        for (int ni = 0; ni < 4; ++ni) {
            int r = m0 + warp_m + mi * 16 + (lane >> 2);
            int c = n0 + warp_n + ni * 8 + (lane & 3) * 2;
            float* p = Cb + (size_t)r * N + c;
            *reinterpret_cast<float2*>(p) =
                make_float2(acc[mi][ni][0], acc[mi][ni][1]);
            *reinterpret_cast<float2*>(p + (size_t)8 * N) =
                make_float2(acc[mi][ni][2], acc[mi][ni][3]);
        }
    }
}

// ---------------------------------------------------------------------------
// SIMT fp32 GEMM (mask) — unchanged from the passing R2 kernel.
// ---------------------------------------------------------------------------
#define BM 128
#define BN 128
#define BK 16
#define TM 8
#define TN 8
#define PAD 4

template<bool BIAS, bool RES>
__global__ __launch_bounds__(256, 2)
void sgemm_kernel(const float* __restrict__ A, const float* __restrict__ B,
                  const float* __restrict__ bias, const float* __restrict__ res,
                  float* __restrict__ C,
                  int M, int N, int K,
                  size_t sA, size_t sB, size_t sC)
{
    const int bz = blockIdx.z;
    const float* Ap = A + (size_t)bz * sA;
    const float* Bp = B + (size_t)bz * sB;
    float*       Cp = C + (size_t)bz * sC;
    const float* Rp = RES ? (res + (size_t)bz * sC) : nullptr;

    const int m0 = blockIdx.y * BM;
    const int n0 = blockIdx.x * BN;

    __shared__ float As[BK][BM + PAD];
    __shared__ float Bs[BK][BN + PAD];

    const int tid = threadIdx.x;
    const int tx  = tid & 15;
    const int ty  = tid >> 4;

    float acc[TM][TN];
#pragma unroll
    for (int i = 0; i < TM; i++)
#pragma unroll
        for (int j = 0; j < TN; j++) acc[i][j] = 0.f;

    for (int k0 = 0; k0 < K; k0 += BK) {
#pragma unroll
        for (int i = 0; i < 2; i++) {
            int v  = tid + i * 256;
            int m  = v >> 2;
            int k4 = (v & 3) << 2;
            float4 f = *reinterpret_cast<const float4*>(
                &Ap[(size_t)(m0 + m) * K + k0 + k4]);
            As[k4 + 0][m] = f.x;
            As[k4 + 1][m] = f.y;
            As[k4 + 2][m] = f.z;
            As[k4 + 3][m] = f.w;
        }
#pragma unroll
        for (int i = 0; i < 2; i++) {
            int v  = tid + i * 256;
            int k  = v >> 5;
            int n4 = (v & 31) << 2;
            float4 f = *reinterpret_cast<const float4*>(
                &Bp[(size_t)(k0 + k) * N + n0 + n4]);
            *reinterpret_cast<float4*>(&Bs[k][n4]) = f;
        }
        __syncthreads();

#pragma unroll
        for (int k = 0; k < BK; k++) {
            float a[TM], bb[TN];
#pragma unroll
            for (int i = 0; i < TM; i++) a[i] = As[k][ty * TM + i];
#pragma unroll
            for (int j = 0; j < TN; j++) bb[j] = Bs[k][tx * TN + j];
#pragma unroll
            for (int i = 0; i < TM; i++)
#pragma unroll
                for (int j = 0; j < TN; j++)
                    acc[i][j] = fmaf(a[i], bb[j], acc[i][j]);
        }
        __syncthreads();
    }

#pragma unroll
    for (int i = 0; i < TM; i++) {
        int m = m0 + ty * TM + i;
        float bv = BIAS ? bias[m] : 0.f;
        size_t base = (size_t)m * N + n0 + tx * TN;
#pragma unroll
        for (int j4 = 0; j4 < TN; j4 += 4) {
            float4 o;
            o.x = acc[i][j4 + 0] + bv;
            o.y = acc[i][j4 + 1] + bv;
            o.z = acc[i][j4 + 2] + bv;
            o.w = acc[i][j4 + 3] + bv;
            if (RES) {
                float4 r = *reinterpret_cast<const float4*>(&Rp[base + j4]);
                o.x += r.x; o.y += r.y; o.z += r.z; o.w += r.w;
            }
            *reinterpret_cast<float4*>(&Cp[base + j4]) = o;
        }
    }
}

// Fused projection GEMM (phi/theta/g in one launch), unchanged.
__global__ __launch_bounds__(256, 2)
void proj_kernel(const float* __restrict__ X,
                 const float* __restrict__ w_phi,   const float* __restrict__ b_phi,
                 const float* __restrict__ w_theta, const float* __restrict__ b_theta,
                 const float* __restrict__ w_g,     const float* __restrict__ b_g,
                 float* __restrict__ proj)
{
    const int which = blockIdx.z / BATCH;
    const int bz    = blockIdx.z % BATCH;
    const float* Ap   = (which == 0) ? w_phi : (which == 1) ? w_theta : w_g;
    const float* bias = (which == 0) ? b_phi : (which == 1) ? b_theta : b_g;
    const float* Bp = X + (size_t)bz * CH * HW;
    float* Cp = proj + ((size_t)which * BATCH + bz) * ICH * HW;

    const int N = HW, K = CH;
    const int m0 = blockIdx.y * BM;
    const int n0 = blockIdx.x * BN;

    __shared__ float As[BK][BM + PAD];
    __shared__ float Bs[BK][BN + PAD];

    const int tid = threadIdx.x;
    const int tx  = tid & 15;
    const int ty  = tid >> 4;

    float acc[TM][TN];
#pragma unroll
    for (int i = 0; i < TM; i++)
#pragma unroll
        for (int j = 0; j < TN; j++) acc[i][j] = 0.f;

    for (int k0 = 0; k0 < K; k0 += BK) {
#pragma unroll
        for (int i = 0; i < 2; i++) {
            int v  = tid + i * 256;
            int m  = v >> 2;
            int k4 = (v & 3) << 2;
            float4 f = *reinterpret_cast<const float4*>(
                &Ap[(size_t)(m0 + m) * K + k0 + k4]);
            As[k4 + 0][m] = f.x;
            As[k4 + 1][m] = f.y;
            As[k4 + 2][m] = f.z;
            As[k4 + 3][m] = f.w;
        }
#pragma unroll
        for (int i = 0; i < 2; i++) {
            int v  = tid + i * 256;
            int k  = v >> 5;
            int n4 = (v & 31) << 2;
            float4 f = *reinterpret_cast<const float4*>(
                &Bp[(size_t)(k0 + k) * N + n0 + n4]);
            *reinterpret_cast<float4*>(&Bs[k][n4]) = f;
        }
        __syncthreads();

#pragma unroll
        for (int k = 0; k < BK; k++) {
            float a[TM], bb[TN];
#pragma unroll
            for (int i = 0; i < TM; i++) a[i] = As[k][ty * TM + i];
#pragma unroll
            for (int j = 0; j < TN; j++) bb[j] = Bs[k][tx * TN + j];
#pragma unroll
            for (int i = 0; i < TM; i++)
#pragma unroll
                for (int j = 0; j < TN; j++)
                    acc[i][j] = fmaf(a[i], bb[j], acc[i][j]);
        }
        __syncthreads();
    }

#pragma unroll
    for (int i = 0; i < TM; i++) {
        int m = m0 + ty * TM + i;
        float bv = bias[m];
        size_t base = (size_t)m * N + n0 + tx * TN;
#pragma unroll
        for (int j4 = 0; j4 < TN; j4 += 4) {
            float4 o;
            o.x = acc[i][j4 + 0] + bv;
            o.y = acc[i][j4 + 1] + bv;
            o.z = acc[i][j4 + 2] + bv;
            o.w = acc[i][j4 + 3] + bv;
            *reinterpret_cast<float4*>(&Cp[base + j4]) = o;
        }
    }
}

// ---------------------------------------------------------------------------
// convQK: phi/theta (f32, viewed [k=2c_v][m]) -> [m][k] bf16 hi/lo, K-major.
// ---------------------------------------------------------------------------
__global__ __launch_bounds__(256)
void convqk_kernel(const float* __restrict__ proj,
                   __nv_bfloat16* __restrict__ dhi, __nv_bfloat16* __restrict__ dlo)
{
    const int m0    = blockIdx.x * 32;
    const int which = blockIdx.y;
    const int b     = blockIdx.z;
    const float* src = proj + ((size_t)which * BATCH + b) * ICH * HW;

    __shared__ float s[32][257];   // [m_local][k]

    const int k    = threadIdx.x;      // 0..255 = c_v
    const int ic   = k >> 1;
    const int half = k & 1;
    const float* sp = src + (size_t)ic * HW + half * NV + m0;
#pragma unroll
    for (int j = 0; j < 8; ++j) {
        float4 v = *reinterpret_cast<const float4*>(sp + j * 4);
        s[j * 4 + 0][k] = v.x;
        s[j * 4 + 1][k] = v.y;
        s[j * 4 + 2][k] = v.z;
        s[j * 4 + 3][k] = v.w;
    }
    __syncthreads();

    const int w = threadIdx.x >> 5;
    const int l = threadIdx.x & 31;
    const size_t base = ((size_t)which * BATCH + b) * (size_t)NV * CV;
#pragma unroll
    for (int i = 0; i < 4; ++i) {
        int m = w * 4 + i;
        __align__(16) __nv_bfloat16 h[8], lo[8];
#pragma unroll
        for (int q = 0; q < 8; ++q) {
            float x = s[m][l * 8 + q];
            h[q]  = __float2bfloat16(x);
            lo[q] = __float2bfloat16(x - __bfloat162float(h[q]));
        }
        size_t off = base + (size_t)(m0 + m) * CV + l * 8;
        *reinterpret_cast<uint4*>(dhi + off) = *reinterpret_cast<uint4*>(h);
        *reinterpret_cast<uint4*>(dlo + off) = *reinterpret_cast<uint4*>(lo);
    }
}

// convG: elementwise f32 -> bf16 hi/lo (layout already K-major [c][m]).
__global__ __launch_bounds__(256)
void convg_kernel(const float* __restrict__ src,
                  __nv_bfloat16* __restrict__ dhi, __nv_bfloat16* __restrict__ dlo)
{
    size_t idx = ((size_t)blockIdx.x * 256 + threadIdx.x) * 4;
    float4 v = *reinterpret_cast<const float4*>(src + idx);
    float xs[4] = {v.x, v.y, v.z, v.w};
    __align__(8) __nv_bfloat16 h[4], l[4];
#pragma unroll
    for (int q = 0; q < 4; ++q) {
        h[q] = __float2bfloat16(xs[q]);
        l[q] = __float2bfloat16(xs[q] - __bfloat162float(h[q]));
    }
    *reinterpret_cast<uint2*>(dhi + idx) = *reinterpret_cast<uint2*>(h);
    *reinterpret_cast<uint2*>(dlo + idx) = *reinterpret_cast<uint2*>(l);
}

// ---------------------------------------------------------------------------
// stats: per contiguous row of attnT (length 2048): max and 1/sum(exp(v-max)).
// ---------------------------------------------------------------------------
__global__ __launch_bounds__(256)
void stats_kernel(const float* __restrict__ attn, float2* __restrict__ stats)
{
    const float* p = attn + (size_t)blockIdx.x * NV;
    const int tid  = threadIdx.x;
    const int lane = tid & 31;
    const int warp = tid >> 5;

    float4 a = *reinterpret_cast<const float4*>(p + tid * 8);
    float4 b = *reinterpret_cast<const float4*>(p + tid * 8 + 4);
    float v[8] = {a.x, a.y, a.z, a.w, b.x, b.y, b.z, b.w};

    float m = v[0];
#pragma unroll
    for (int i = 1; i < 8; i++) m = fmaxf(m, v[i]);
#pragma unroll
    for (int o = 16; o > 0; o >>= 1)
        m = fmaxf(m, __shfl_xor_sync(0xffffffffu, m, o));

    __shared__ float smax[8];
    __shared__ float ssum[8];
    if (lane == 0) smax[warp] = m;
    __syncthreads();
    m = smax[0];
#pragma unroll
    for (int i = 1; i < 8; i++) m = fmaxf(m, smax[i]);

    float s = 0.f;
#pragma unroll
    for (int i = 0; i < 8; i++) s += expf(v[i] - m);
#pragma unroll
    for (int o = 16; o > 0; o >>= 1)
        s += __shfl_xor_sync(0xffffffffu, s, o);
    if (lane == 0) ssum[warp] = s;
    __syncthreads();
    s = ssum[0];
#pragma unroll
    for (int i = 1; i < 8; i++) s += ssum[i];

    if (tid == 0) stats[blockIdx.x] = make_float2(m, 1.f / s);
}

// ---------------------------------------------------------------------------
// normT: attn[m][n] f32 -> softmaxed + transposed bf16 hi/lo [n][m].
// ---------------------------------------------------------------------------
__global__ __launch_bounds__(256)
void normt_kernel(const float* __restrict__ attn, const float2* __restrict__ stats,
                  __nv_bfloat16* __restrict__ thi, __nv_bfloat16* __restrict__ tlo)
{
    const int b  = blockIdx.z;
    const int m0 = blockIdx.x * 32;
    const int n0 = blockIdx.y * 32;
    __shared__ float s[32][33];   // [n_local][m_local]

    const float* src = attn + (size_t)b * NV * NV;
    {
        int i  = threadIdx.x >> 3;   // m_local
        int c4 = threadIdx.x & 7;    // n chunk of 4
        float2 st = stats[(size_t)b * NV + m0 + i];
        float4 v = *reinterpret_cast<const float4*>(
            src + (size_t)(m0 + i) * NV + n0 + c4 * 4);
        s[c4 * 4 + 0][i] = expf(v.x - st.x) * st.y;
        s[c4 * 4 + 1][i] = expf(v.y - st.x) * st.y;
        s[c4 * 4 + 2][i] = expf(v.z - st.x) * st.y;
        s[c4 * 4 + 3][i] = expf(v.w - st.x) * st.y;
    }
    __syncthreads();
    {
        int nl = threadIdx.x >> 3;   // n_local
        int c  = threadIdx.x & 7;    // m chunk of 4
        __align__(8) __nv_bfloat16 h[4], l[4];
#pragma unroll
        for (int q = 0; q < 4; ++q) {
            float x = s[nl][c * 4 + q];
            h[q] = __float2bfloat16(x);
            l[q] = __float2bfloat16(x - __bfloat162float(h[q]));
        }
        size_t off = (size_t)b * NV * NV + (size_t)(n0 + nl) * NV + m0 + c * 4;
        *reinterpret_cast<uint2*>(thi + off) = *reinterpret_cast<uint2*>(h);
        *reinterpret_cast<uint2*>(tlo + off) = *reinterpret_cast<uint2*>(l);
    }
}

// ---------------------------------------------------------------------------
extern "C" void kernel_launch(void* const* d_in, const int* in_sizes, int n_in,
                              void* d_out, int out_size)
{
    const float* x       = (const float*)d_in[0];
    const float* w_phi   = (const float*)d_in[1];
    const float* b_phi   = (const float*)d_in[2];
    const float* w_theta = (const float*)d_in[3];
    const float* b_theta = (const float*)d_in[4];
    const float* w_g     = (const float*)d_in[5];
    const float* b_g     = (const float*)d_in[6];
    const float* w_mask  = (const float*)d_in[7];
    const float* b_mask  = (const float*)d_in[8];
    float*       out     = (float*)d_out;

    static float* proj = nullptr;
    static float* attn = nullptr;
    static float* obuf = nullptr;
    static __nv_bfloat16 *qkhi = nullptr, *qklo = nullptr;
    static __nv_bfloat16 *ghi = nullptr, *glo = nullptr;
    static __nv_bfloat16 *athi = nullptr, *atlo = nullptr;
    static float2* stats = nullptr;
    if (proj == nullptr) {
        cudaGetSymbolAddress((void**)&proj,  g_proj);
        cudaGetSymbolAddress((void**)&attn,  g_attn);
        cudaGetSymbolAddress((void**)&obuf,  g_out);
        cudaGetSymbolAddress((void**)&qkhi,  g_qkT_hi);
        cudaGetSymbolAddress((void**)&qklo,  g_qkT_lo);
        cudaGetSymbolAddress((void**)&ghi,   g_g_hi);
        cudaGetSymbolAddress((void**)&glo,   g_g_lo);
        cudaGetSymbolAddress((void**)&athi,  g_at_hi);
        cudaGetSymbolAddress((void**)&atlo,  g_at_lo);
        cudaGetSymbolAddress((void**)&stats, g_stats);
        cudaFuncSetAttribute(mma_gemm, cudaFuncAttributeMaxDynamicSharedMemorySize,
                             MM_SMEM);
    }

    const size_t sX    = (size_t)CH * HW;
    const size_t sProj = (size_t)ICH * HW;      // == CV * NV
    const size_t sAttn = (size_t)NV * NV;
    const size_t sQK   = (size_t)NV * CV;

    // 1) projections
    {
        dim3 grid(HW / BN, ICH / BM, 3 * BATCH);
        proj_kernel<<<grid, 256>>>(x, w_phi, b_phi, w_theta, b_theta, w_g, b_g, proj);
    }
    // 2) converts
    {
        dim3 grid(NV / 32, 2, BATCH);
        convqk_kernel<<<grid, 256>>>(proj, qkhi, qklo);
        convg_kernel<<<(unsigned)((size_t)BATCH * CV * NV / 1024), 256>>>(
            proj + (size_t)2 * BATCH * ICH * HW, ghi, glo);
    }
    // 3) GEMM2: attnT = phiT @ thetaT^T  (M=N=2048, K=256)
    {
        dim3 grid(NV / 128, NV / 128, BATCH);
        mma_gemm<<<grid, 256, MM_SMEM>>>(
            qkhi, qklo,
            qkhi + (size_t)BATCH * sQK,
            qklo + (size_t)BATCH * sQK,
            attn, NV, NV, CV, sQK, sQK, sAttn);
    }
    // 4) softmax stats
    stats_kernel<<<BATCH * NV, 256>>>(attn, stats);
    // 5) normalize + transpose + split
    {
        dim3 grid(NV / 32, NV / 32, BATCH);
        normt_kernel<<<grid, 256>>>(attn, stats, athi, atlo);
    }
    // 6) GEMM4: OUT_v = g_v @ P  (M=256, N=2048, K=2048)
    {
        dim3 grid(NV / 128, CV / 128, BATCH);
        mma_gemm<<<grid, 256, MM_SMEM>>>(
            ghi, glo, athi, atlo, obuf,
            CV, NV, NV, (size_t)CV * NV, sAttn, (size_t)CV * NV);
    }
    // 7) mask = w_mask @ OUT + b_mask + x
    {
        dim3 grid(HW / BN, CH / BM, BATCH);
        sgemm_kernel<true, true><<<grid, 256>>>(
            w_mask, obuf, b_mask, x, out, CH, HW, ICH, 0, sProj, sX);
    }
}

// round 7
// speedup vs baseline: 2.0922x; 1.1778x over previous
#include <cuda_runtime.h>
#include <cuda_bf16.h>
#include <math.h>
#include <stdint.h>

// ---------------------------------------------------------------------------
// NonLocal block, B=16, C=256, IC=128, H=W=64.  All five GEMMs on mma.sync
// bf16 split-3 tensor path (sm_100 base target; tcgen05 unavailable).
//   0) convW: split all 4 weight matrices to bf16 hi/lo
//   1) convX: x -> xT [hw][c] bf16 hi/lo (transpose + split)
//   2) proj (tensor): phi/theta -> f32 natural layout; g -> split bf16 (K-major)
//   3) convqk: phi,theta f32 -> [m][k] bf16 hi/lo (view transpose)
//   4) GEMM2 (tensor): attnT[m][n] (f32)
//   5) stats + normT (softmax, transpose, split)
//   6) GEMM4 (tensor, swapped A/B): OUTT[n][c_v] split bf16
//   7) deint: OUTT -> outT [hw][ic] split bf16
//   8) mask (tensor, bias+residual): out = w_mask @ OUT + b_mask + x
// ---------------------------------------------------------------------------

#define BATCH 16
#define CH    256
#define ICH   128
#define HW    4096
#define NV    2048
#define CV    256

// ------------------------------- scratch ----------------------------------
__device__ __align__(16) __nv_bfloat16 g_xT_hi[(size_t)BATCH * HW * CH];
__device__ __align__(16) __nv_bfloat16 g_xT_lo[(size_t)BATCH * HW * CH];
__device__ __align__(16) __nv_bfloat16 g_w_hi[4 * 32768];
__device__ __align__(16) __nv_bfloat16 g_w_lo[4 * 32768];
__device__ __align__(16) float g_projf[(size_t)2 * BATCH * ICH * HW];       // phi, theta
__device__ __align__(16) float g_attn [(size_t)BATCH * NV * NV];
__device__ __align__(16) __nv_bfloat16 g_qkT_hi[(size_t)2 * BATCH * NV * CV];
__device__ __align__(16) __nv_bfloat16 g_qkT_lo[(size_t)2 * BATCH * NV * CV];
__device__ __align__(16) __nv_bfloat16 g_g_hi [(size_t)BATCH * CV * NV];
__device__ __align__(16) __nv_bfloat16 g_g_lo [(size_t)BATCH * CV * NV];
__device__ __align__(16) __nv_bfloat16 g_at_hi[(size_t)BATCH * NV * NV];
__device__ __align__(16) __nv_bfloat16 g_at_lo[(size_t)BATCH * NV * NV];
__device__ __align__(16) __nv_bfloat16 g_oT_hi[(size_t)BATCH * NV * CV];    // OUTT [n][c_v]
__device__ __align__(16) __nv_bfloat16 g_oT_lo[(size_t)BATCH * NV * CV];
__device__ __align__(16) __nv_bfloat16 g_ot_hi[(size_t)BATCH * HW * ICH];   // outT [hw][ic]
__device__ __align__(16) __nv_bfloat16 g_ot_lo[(size_t)BATCH * HW * ICH];
__device__ __align__(16) float2 g_stats[(size_t)BATCH * NV];

// --------------------------- helpers ---------------------------------------
__device__ __forceinline__ uint32_t smem_u32(const void* p) {
    uint32_t a;
    asm("{ .reg .u64 t; cvta.to.shared.u64 t, %1; cvt.u32.u64 %0, t; }"
        : "=r"(a) : "l"(p));
    return a;
}
__device__ __forceinline__ void ldsm4(uint32_t* r, uint32_t a) {
    asm volatile("ldmatrix.sync.aligned.m8n8.x4.shared.b16 {%0,%1,%2,%3}, [%4];"
                 : "=r"(r[0]), "=r"(r[1]), "=r"(r[2]), "=r"(r[3]) : "r"(a));
}
__device__ __forceinline__ void mma16816(float* d, const uint32_t* a, const uint32_t* b) {
    asm volatile(
        "mma.sync.aligned.m16n8k16.row.col.f32.bf16.bf16.f32 "
        "{%0,%1,%2,%3}, {%4,%5,%6,%7}, {%8,%9}, {%0,%1,%2,%3};"
        : "+f"(d[0]), "+f"(d[1]), "+f"(d[2]), "+f"(d[3])
        : "r"(a[0]), "r"(a[1]), "r"(a[2]), "r"(a[3]), "r"(b[0]), "r"(b[1]));
}
__device__ __forceinline__ void cp16(uint32_t dst, const void* src) {
    asm volatile("cp.async.cg.shared.global [%0], [%1], 16;" :: "r"(dst), "l"(src));
}
__device__ __forceinline__ uint32_t pack_bf16x2(__nv_bfloat16 a, __nv_bfloat16 b) {
    __nv_bfloat162 t = __nv_bfloat162(a, b);
    return *reinterpret_cast<uint32_t*>(&t);
}

// ---------------------------------------------------------------------------
// Split-bf16 TN GEMM via mma.sync:
//   C[bz][m][n] = sum_k (Ahi+Alo)[m][k]*(Bhi+Blo)[n][k]   (hi*hi+hi*lo+lo*hi)
// A,B K-major bf16 (ld=K).  Epilogue variants:
//   SPLIT=false: f32 C (+bias[m]) (+res)
//   SPLIT=true : bf16 hi/lo pair (+bias[m])
// CTA tile 128x128x64, 8 warps (64x32 each), 3-stage cp.async pipeline.
// ---------------------------------------------------------------------------
#define MM_BK     64
#define MM_STAGES 3
#define TILE16K   16384          // 128 rows * 128 B
#define STG_BYTES (4 * TILE16K)  // Ahi, Alo, Bhi, Blo
#define MM_SMEM   (MM_STAGES * STG_BYTES)

template<bool BIAS, bool RES, bool SPLIT>
__global__ __launch_bounds__(256, 1)
void mma_gemm(const __nv_bfloat16* __restrict__ Ahi, const __nv_bfloat16* __restrict__ Alo,
              const __nv_bfloat16* __restrict__ Bhi, const __nv_bfloat16* __restrict__ Blo,
              const float* __restrict__ bias, const float* __restrict__ res,
              float* __restrict__ C,
              __nv_bfloat16* __restrict__ Chi, __nv_bfloat16* __restrict__ Clo,
              int M, int N, int K, size_t sA, size_t sB, size_t sC)
{
    extern __shared__ __align__(1024) char smem[];
    const int tid  = threadIdx.x;
    const int wid  = tid >> 5;
    const int lane = tid & 31;
    const int bz = blockIdx.z;
    const int m0 = blockIdx.y * 128;
    const int n0 = blockIdx.x * 128;
    const int warp_m = (wid >> 2) * 64;   // 0 or 64
    const int warp_n = (wid & 3) * 32;    // 0,32,64,96

    const __nv_bfloat16* tp[4];
    tp[0] = Ahi + (size_t)bz * sA + (size_t)m0 * K;
    tp[1] = Alo + (size_t)bz * sA + (size_t)m0 * K;
    tp[2] = Bhi + (size_t)bz * sB + (size_t)n0 * K;
    tp[3] = Blo + (size_t)bz * sB + (size_t)n0 * K;

    const uint32_t sbase = smem_u32(smem);
    const int nk = K / MM_BK;

    auto load_stage = [&](int it) {
        const int k0 = it * MM_BK;
        const uint32_t sdst = sbase + (uint32_t)(it % MM_STAGES) * STG_BYTES;
#pragma unroll
        for (int j = 0; j < 16; ++j) {
            int idx  = j * 256 + tid;
            int tile = idx >> 10;
            int row  = (idx >> 3) & 127;
            int ck   = idx & 7;
            const __nv_bfloat16* src = tp[tile] + (size_t)row * K + k0 + ck * 8;
            uint32_t dst = sdst + (uint32_t)tile * TILE16K + row * 128 +
                           (((uint32_t)(ck ^ (row & 7))) << 4);
            cp16(dst, src);
        }
        asm volatile("cp.async.commit_group;" ::: "memory");
    };

    float acc[4][4][4];
#pragma unroll
    for (int mi = 0; mi < 4; ++mi)
#pragma unroll
        for (int ni = 0; ni < 4; ++ni)
#pragma unroll
            for (int q = 0; q < 4; ++q) acc[mi][ni][q] = 0.f;

    const int npre = (MM_STAGES - 1 < nk) ? MM_STAGES - 1 : nk;
    for (int s = 0; s < npre; ++s) load_stage(s);

    const int a_rl = lane & 15;
    const int a_ck = (lane >> 4);
    const int b_rl = ((lane >> 4) << 3) + (lane & 7);
    const int b_ck = (lane >> 3) & 1;

    for (int it = 0; it < nk; ++it) {
        if (it + MM_STAGES - 1 < nk) {
            load_stage(it + MM_STAGES - 1);
            asm volatile("cp.async.wait_group %0;" :: "n"(MM_STAGES - 2) : "memory");
        } else {
            asm volatile("cp.async.wait_group 0;" ::: "memory");
        }
        __syncthreads();

        const uint32_t sa = sbase + (uint32_t)(it % MM_STAGES) * STG_BYTES;
        const uint32_t sb = sa + 2 * TILE16K;

#pragma unroll
        for (int ks = 0; ks < 4; ++ks) {
            uint32_t ah[4][4], al[4][4];
            const int achunk = ks * 2 + a_ck;
#pragma unroll
            for (int mi = 0; mi < 4; ++mi) {
                int mrow = warp_m + mi * 16 + a_rl;
                uint32_t ad = sa + mrow * 128 + ((uint32_t)(achunk ^ (mrow & 7)) << 4);
                ldsm4(ah[mi], ad);
                ldsm4(al[mi], ad + TILE16K);
            }
            uint32_t bh[2][4], bl[2][4];
            const int bchunk = ks * 2 + b_ck;
#pragma unroll
            for (int nj = 0; nj < 2; ++nj) {
                int nrow = warp_n + nj * 16 + b_rl;
                uint32_t bd = sb + nrow * 128 + ((uint32_t)(bchunk ^ (nrow & 7)) << 4);
                ldsm4(bh[nj], bd);
                ldsm4(bl[nj], bd + TILE16K);
            }
#pragma unroll
            for (int mi = 0; mi < 4; ++mi)
#pragma unroll
                for (int ni = 0; ni < 4; ++ni) {
                    const uint32_t* ph = &bh[ni >> 1][(ni & 1) * 2];
                    const uint32_t* pl = &bl[ni >> 1][(ni & 1) * 2];
                    mma16816(acc[mi][ni], ah[mi], ph);   // hi*hi
                    mma16816(acc[mi][ni], ah[mi], pl);   // hi*lo
                    mma16816(acc[mi][ni], al[mi], ph);   // lo*hi
                }
        }
        __syncthreads();
    }

    // ---- epilogue ----
#pragma unroll
    for (int mi = 0; mi < 4; ++mi) {
#pragma unroll
        for (int ni = 0; ni < 4; ++ni) {
            int r = m0 + warp_m + mi * 16 + (lane >> 2);
            int c = n0 + warp_n + ni * 8 + (lane & 3) * 2;
            float v0 = acc[mi][ni][0], v1 = acc[mi][ni][1];
            float v2 = acc[mi][ni][2], v3 = acc[mi][ni][3];
            if (BIAS) {
                float b0 = bias[r], b1 = bias[r + 8];
                v0 += b0; v1 += b0; v2 += b1; v3 += b1;
            }
            if (SPLIT) {
                __nv_bfloat16 h0 = __float2bfloat16(v0);
                __nv_bfloat16 h1 = __float2bfloat16(v1);
                __nv_bfloat16 h2 = __float2bfloat16(v2);
                __nv_bfloat16 h3 = __float2bfloat16(v3);
                __nv_bfloat16 l0 = __float2bfloat16(v0 - __bfloat162float(h0));
                __nv_bfloat16 l1 = __float2bfloat16(v1 - __bfloat162float(h1));
                __nv_bfloat16 l2 = __float2bfloat16(v2 - __bfloat162float(h2));
                __nv_bfloat16 l3 = __float2bfloat16(v3 - __bfloat162float(h3));
                size_t p0 = (size_t)bz * sC + (size_t)r * N + c;
                size_t p1 = (size_t)bz * sC + (size_t)(r + 8) * N + c;
                *reinterpret_cast<uint32_t*>(Chi + p0) = pack_bf16x2(h0, h1);
                *reinterpret_cast<uint32_t*>(Chi + p1) = pack_bf16x2(h2, h3);
                *reinterpret_cast<uint32_t*>(Clo + p0) = pack_bf16x2(l0, l1);
                *reinterpret_cast<uint32_t*>(Clo + p1) = pack_bf16x2(l2, l3);
            } else {
                float* p = C + (size_t)bz * sC + (size_t)r * N + c;
                if (RES) {
                    const float* rp = res + (size_t)bz * sC + (size_t)r * N + c;
                    float2 r0 = *reinterpret_cast<const float2*>(rp);
                    float2 r1 = *reinterpret_cast<const float2*>(rp + (size_t)8 * N);
                    v0 += r0.x; v1 += r0.y; v2 += r1.x; v3 += r1.y;
                }
                *reinterpret_cast<float2*>(p) = make_float2(v0, v1);
                *reinterpret_cast<float2*>(p + (size_t)8 * N) = make_float2(v2, v3);
            }
        }
    }
}

// ---------------------------------------------------------------------------
// convW: split 4 weight matrices (each 32768 f32) into bf16 hi/lo.
// ---------------------------------------------------------------------------
__global__ __launch_bounds__(256)
void convw_kernel(const float* __restrict__ w0, const float* __restrict__ w1,
                  const float* __restrict__ w2, const float* __restrict__ w3,
                  __nv_bfloat16* __restrict__ hi, __nv_bfloat16* __restrict__ lo)
{
    int gid = blockIdx.x * 256 + threadIdx.x;        // 32768 threads
    int seg = gid >> 13;
    int off = (gid & 8191) * 4;
    const float* src = (seg == 0) ? w0 : (seg == 1) ? w1 : (seg == 2) ? w2 : w3;
    float4 v = *reinterpret_cast<const float4*>(src + off);
    float xs[4] = {v.x, v.y, v.z, v.w};
    __align__(8) __nv_bfloat16 h[4], l[4];
#pragma unroll
    for (int q = 0; q < 4; ++q) {
        h[q] = __float2bfloat16(xs[q]);
        l[q] = __float2bfloat16(xs[q] - __bfloat162float(h[q]));
    }
    size_t d = (size_t)seg * 32768 + off;
    *reinterpret_cast<uint2*>(hi + d) = *reinterpret_cast<uint2*>(h);
    *reinterpret_cast<uint2*>(lo + d) = *reinterpret_cast<uint2*>(l);
}

// ---------------------------------------------------------------------------
// convX: x [b][c][hw] f32 -> xT [b][hw][c] bf16 hi/lo (transpose + split).
// ---------------------------------------------------------------------------
__global__ __launch_bounds__(256)
void convx_kernel(const float* __restrict__ x,
                  __nv_bfloat16* __restrict__ hi, __nv_bfloat16* __restrict__ lo)
{
    const int b   = blockIdx.z;
    const int hw0 = blockIdx.x * 32;
    const int c0  = blockIdx.y * 32;
    __shared__ float s[32][33];   // [hw_local][c_local]

    const float* src = x + (size_t)b * CH * HW;
    {
        int i  = threadIdx.x >> 3;   // c_local
        int c4 = threadIdx.x & 7;    // hw chunk
        float4 v = *reinterpret_cast<const float4*>(
            src + (size_t)(c0 + i) * HW + hw0 + c4 * 4);
        s[c4 * 4 + 0][i] = v.x;
        s[c4 * 4 + 1][i] = v.y;
        s[c4 * 4 + 2][i] = v.z;
        s[c4 * 4 + 3][i] = v.w;
    }
    __syncthreads();
    {
        int nl = threadIdx.x >> 3;   // hw_local
        int cc = threadIdx.x & 7;    // c chunk of 4
        __align__(8) __nv_bfloat16 h[4], l[4];
#pragma unroll
        for (int q = 0; q < 4; ++q) {
            float v = s[nl][cc * 4 + q];
            h[q] = __float2bfloat16(v);
            l[q] = __float2bfloat16(v - __bfloat162float(h[q]));
        }
        size_t off = (size_t)b * HW * CH + (size_t)(hw0 + nl) * CH + c0 + cc * 4;
        *reinterpret_cast<uint2*>(hi + off) = *reinterpret_cast<uint2*>(h);
        *reinterpret_cast<uint2*>(lo + off) = *reinterpret_cast<uint2*>(l);
    }
}

// ---------------------------------------------------------------------------
// convQK: phi/theta (f32 natural [ic][hw]) -> [m][k=c_v] bf16 hi/lo, K-major.
// ---------------------------------------------------------------------------
__global__ __launch_bounds__(256)
void convqk_kernel(const float* __restrict__ proj,
                   __nv_bfloat16* __restrict__ dhi, __nv_bfloat16* __restrict__ dlo)
{
    const int m0    = blockIdx.x * 32;
    const int which = blockIdx.y;
    const int b     = blockIdx.z;
    const float* src = proj + ((size_t)which * BATCH + b) * ICH * HW;

    __shared__ float s[32][257];   // [m_local][k]

    const int k    = threadIdx.x;      // 0..255 = c_v
    const int ic   = k >> 1;
    const int half = k & 1;
    const float* sp = src + (size_t)ic * HW + half * NV + m0;
#pragma unroll
    for (int j = 0; j < 8; ++j) {
        float4 v = *reinterpret_cast<const float4*>(sp + j * 4);
        s[j * 4 + 0][k] = v.x;
        s[j * 4 + 1][k] = v.y;
        s[j * 4 + 2][k] = v.z;
        s[j * 4 + 3][k] = v.w;
    }
    __syncthreads();

    const int w = threadIdx.x >> 5;
    const int l = threadIdx.x & 31;
    const size_t base = ((size_t)which * BATCH + b) * (size_t)NV * CV;
#pragma unroll
    for (int i = 0; i < 4; ++i) {
        int m = w * 4 + i;
        __align__(16) __nv_bfloat16 h[8], lo[8];
#pragma unroll
        for (int q = 0; q < 8; ++q) {
            float x = s[m][l * 8 + q];
            h[q]  = __float2bfloat16(x);
            lo[q] = __float2bfloat16(x - __bfloat162float(h[q]));
        }
        size_t off = base + (size_t)(m0 + m) * CV + l * 8;
        *reinterpret_cast<uint4*>(dhi + off) = *reinterpret_cast<uint4*>(h);
        *reinterpret_cast<uint4*>(dlo + off) = *reinterpret_cast<uint4*>(lo);
    }
}

// ---------------------------------------------------------------------------
// stats: per contiguous row of attnT (length 2048): max and 1/sum(exp(v-max)).
// ---------------------------------------------------------------------------
__global__ __launch_bounds__(256)
void stats_kernel(const float* __restrict__ attn, float2* __restrict__ stats)
{
    const float* p = attn + (size_t)blockIdx.x * NV;
    const int tid  = threadIdx.x;
    const int lane = tid & 31;
    const int warp = tid >> 5;

    float4 a = *reinterpret_cast<const float4*>(p + tid * 8);
    float4 b = *reinterpret_cast<const float4*>(p + tid * 8 + 4);
    float v[8] = {a.x, a.y, a.z, a.w, b.x, b.y, b.z, b.w};

    float m = v[0];
#pragma unroll
    for (int i = 1; i < 8; i++) m = fmaxf(m, v[i]);
#pragma unroll
    for (int o = 16; o > 0; o >>= 1)
        m = fmaxf(m, __shfl_xor_sync(0xffffffffu, m, o));

    __shared__ float smax[8];
    __shared__ float ssum[8];
    if (lane == 0) smax[warp] = m;
    __syncthreads();
    m = smax[0];
#pragma unroll
    for (int i = 1; i < 8; i++) m = fmaxf(m, smax[i]);

    float s = 0.f;
#pragma unroll
    for (int i = 0; i < 8; i++) s += expf(v[i] - m);
#pragma unroll
    for (int o = 16; o > 0; o >>= 1)
        s += __shfl_xor_sync(0xffffffffu, s, o);
    if (lane == 0) ssum[warp] = s;
    __syncthreads();
    s = ssum[0];
#pragma unroll
    for (int i = 1; i < 8; i++) s += ssum[i];

    if (tid == 0) stats[blockIdx.x] = make_float2(m, 1.f / s);
}

// ---------------------------------------------------------------------------
// normT: attn[m][n] f32 -> softmaxed + transposed bf16 hi/lo [n][m].
// ---------------------------------------------------------------------------
__global__ __launch_bounds__(256)
void normt_kernel(const float* __restrict__ attn, const float2* __restrict__ stats,
                  __nv_bfloat16* __restrict__ thi, __nv_bfloat16* __restrict__ tlo)
{
    const int b  = blockIdx.z;
    const int m0 = blockIdx.x * 32;
    const int n0 = blockIdx.y * 32;
    __shared__ float s[32][33];   // [n_local][m_local]

    const float* src = attn + (size_t)b * NV * NV;
    {
        int i  = threadIdx.x >> 3;   // m_local
        int c4 = threadIdx.x & 7;    // n chunk of 4
        float2 st = stats[(size_t)b * NV + m0 + i];
        float4 v = *reinterpret_cast<const float4*>(
            src + (size_t)(m0 + i) * NV + n0 + c4 * 4);
        s[c4 * 4 + 0][i] = expf(v.x - st.x) * st.y;
        s[c4 * 4 + 1][i] = expf(v.y - st.x) * st.y;
        s[c4 * 4 + 2][i] = expf(v.z - st.x) * st.y;
        s[c4 * 4 + 3][i] = expf(v.w - st.x) * st.y;
    }
    __syncthreads();
    {
        int nl = threadIdx.x >> 3;   // n_local
        int c  = threadIdx.x & 7;    // m chunk of 4
        __align__(8) __nv_bfloat16 h[4], l[4];
#pragma unroll
        for (int q = 0; q < 4; ++q) {
            float x = s[nl][c * 4 + q];
            h[q] = __float2bfloat16(x);
            l[q] = __float2bfloat16(x - __bfloat162float(h[q]));
        }
        size_t off = (size_t)b * NV * NV + (size_t)(n0 + nl) * NV + m0 + c * 4;
        *reinterpret_cast<uint2*>(thi + off) = *reinterpret_cast<uint2*>(h);
        *reinterpret_cast<uint2*>(tlo + off) = *reinterpret_cast<uint2*>(l);
    }
}

// ---------------------------------------------------------------------------
// deint: OUTT [b][m][c_v] -> outT [b][hw][ic] with outT[half*2048+m][ic] =
// OUTT[m][2*ic+half].  Fully coalesced bf16 shuffling.
// ---------------------------------------------------------------------------
__global__ __launch_bounds__(256)
void deint_kernel(const __nv_bfloat16* __restrict__ shi, const __nv_bfloat16* __restrict__ slo,
                  __nv_bfloat16* __restrict__ dhi, __nv_bfloat16* __restrict__ dlo)
{
    int gid = blockIdx.x * 256 + threadIdx.x;
    int q = gid & 31;
    int m = (gid >> 5) & 2047;
    int b = gid >> 16;

    size_t soff = ((size_t)b * NV + m) * CV + q * 8;
    uint4 vh = *reinterpret_cast<const uint4*>(shi + soff);
    uint4 vl = *reinterpret_cast<const uint4*>(slo + soff);
    const uint16_t* ph = reinterpret_cast<const uint16_t*>(&vh);
    const uint16_t* pl = reinterpret_cast<const uint16_t*>(&vl);

    __align__(8) uint16_t eh[4], oh[4], el[4], ol[4];
#pragma unroll
    for (int i = 0; i < 4; ++i) {
        eh[i] = ph[2 * i];     oh[i] = ph[2 * i + 1];
        el[i] = pl[2 * i];     ol[i] = pl[2 * i + 1];
    }
    size_t d0 = ((size_t)b * HW + m) * ICH + q * 4;
    size_t d1 = ((size_t)b * HW + NV + m) * ICH + q * 4;
    *reinterpret_cast<uint2*>(dhi + d0) = *reinterpret_cast<uint2*>(eh);
    *reinterpret_cast<uint2*>(dhi + d1) = *reinterpret_cast<uint2*>(oh);
    *reinterpret_cast<uint2*>(dlo + d0) = *reinterpret_cast<uint2*>(el);
    *reinterpret_cast<uint2*>(dlo + d1) = *reinterpret_cast<uint2*>(ol);
}

// ---------------------------------------------------------------------------
extern "C" void kernel_launch(void* const* d_in, const int* in_sizes, int n_in,
                              void* d_out, int out_size)
{
    const float* x       = (const float*)d_in[0];
    const float* w_phi   = (const float*)d_in[1];
    const float* b_phi   = (const float*)d_in[2];
    const float* w_theta = (const float*)d_in[3];
    const float* b_theta = (const float*)d_in[4];
    const float* w_g     = (const float*)d_in[5];
    const float* b_g     = (const float*)d_in[6];
    const float* w_mask  = (const float*)d_in[7];
    const float* b_mask  = (const float*)d_in[8];
    float*       out     = (float*)d_out;

    static __nv_bfloat16 *xthi = nullptr, *xtlo = nullptr, *whi = nullptr, *wlo = nullptr;
    static float *projf = nullptr, *attn = nullptr;
    static __nv_bfloat16 *qkhi = nullptr, *qklo = nullptr;
    static __nv_bfloat16 *ghi = nullptr, *glo = nullptr;
    static __nv_bfloat16 *athi = nullptr, *atlo = nullptr;
    static __nv_bfloat16 *othi = nullptr, *otlo = nullptr;     // OUTT
    static __nv_bfloat16 *obhi = nullptr, *oblo = nullptr;     // outT deint
    static float2* stats = nullptr;
    if (projf == nullptr) {
        cudaGetSymbolAddress((void**)&xthi,  g_xT_hi);
        cudaGetSymbolAddress((void**)&xtlo,  g_xT_lo);
        cudaGetSymbolAddress((void**)&whi,   g_w_hi);
        cudaGetSymbolAddress((void**)&wlo,   g_w_lo);
        cudaGetSymbolAddress((void**)&projf, g_projf);
        cudaGetSymbolAddress((void**)&attn,  g_attn);
        cudaGetSymbolAddress((void**)&qkhi,  g_qkT_hi);
        cudaGetSymbolAddress((void**)&qklo,  g_qkT_lo);
        cudaGetSymbolAddress((void**)&ghi,   g_g_hi);
        cudaGetSymbolAddress((void**)&glo,   g_g_lo);
        cudaGetSymbolAddress((void**)&athi,  g_at_hi);
        cudaGetSymbolAddress((void**)&atlo,  g_at_lo);
        cudaGetSymbolAddress((void**)&othi,  g_oT_hi);
        cudaGetSymbolAddress((void**)&otlo,  g_oT_lo);
        cudaGetSymbolAddress((void**)&obhi,  g_ot_hi);
        cudaGetSymbolAddress((void**)&oblo,  g_ot_lo);
        cudaGetSymbolAddress((void**)&stats, g_stats);
        cudaFuncSetAttribute(mma_gemm<false, false, false>,
                             cudaFuncAttributeMaxDynamicSharedMemorySize, MM_SMEM);
        cudaFuncSetAttribute(mma_gemm<false, false, true>,
                             cudaFuncAttributeMaxDynamicSharedMemorySize, MM_SMEM);
        cudaFuncSetAttribute(mma_gemm<true, false, false>,
                             cudaFuncAttributeMaxDynamicSharedMemorySize, MM_SMEM);
        cudaFuncSetAttribute(mma_gemm<true, false, true>,
                             cudaFuncAttributeMaxDynamicSharedMemorySize, MM_SMEM);
        cudaFuncSetAttribute(mma_gemm<true, true, false>,
                             cudaFuncAttributeMaxDynamicSharedMemorySize, MM_SMEM);
    }

    const size_t sX    = (size_t)CH * HW;       // 1048576
    const size_t sProj = (size_t)ICH * HW;      // 524288 == CV*NV
    const size_t sAttn = (size_t)NV * NV;
    const size_t sQK   = (size_t)NV * CV;

    __nv_bfloat16* wphi_hi = whi;             __nv_bfloat16* wphi_lo = wlo;
    __nv_bfloat16* wth_hi  = whi + 32768;     __nv_bfloat16* wth_lo  = wlo + 32768;
    __nv_bfloat16* wg_hi   = whi + 65536;     __nv_bfloat16* wg_lo   = wlo + 65536;
    __nv_bfloat16* wm_hi   = whi + 98304;     __nv_bfloat16* wm_lo   = wlo + 98304;

    // 0) split weights
    convw_kernel<<<128, 256>>>(w_phi, w_theta, w_g, w_mask, whi, wlo);
    // 1) transpose+split x -> xT [hw][c]
    {
        dim3 grid(HW / 32, CH / 32, BATCH);
        convx_kernel<<<grid, 256>>>(x, xthi, xtlo);
    }
    // 2) projections (tensor): M=128, N=4096, K=256
    {
        dim3 grid(HW / 128, 1, BATCH);
        mma_gemm<true, false, false><<<grid, 256, MM_SMEM>>>(
            wphi_hi, wphi_lo, xthi, xtlo, b_phi, nullptr,
            projf, nullptr, nullptr, ICH, HW, CH, 0, sX, sProj);
        mma_gemm<true, false, false><<<grid, 256, MM_SMEM>>>(
            wth_hi, wth_lo, xthi, xtlo, b_theta, nullptr,
            projf + (size_t)BATCH * sProj, nullptr, nullptr, ICH, HW, CH, 0, sX, sProj);
        mma_gemm<true, false, true><<<grid, 256, MM_SMEM>>>(
            wg_hi, wg_lo, xthi, xtlo, b_g, nullptr,
            nullptr, ghi, glo, ICH, HW, CH, 0, sX, sProj);
    }
    // 3) convqk: phi/theta -> [m][k] split
    {
        dim3 grid(NV / 32, 2, BATCH);
        convqk_kernel<<<grid, 256>>>(projf, qkhi, qklo);
    }
    // 4) GEMM2: attnT = phiT @ thetaT^T (M=N=2048, K=256)
    {
        dim3 grid(NV / 128, NV / 128, BATCH);
        mma_gemm<false, false, false><<<grid, 256, MM_SMEM>>>(
            qkhi, qklo, qkhi + (size_t)BATCH * sQK, qklo + (size_t)BATCH * sQK,
            nullptr, nullptr, attn, nullptr, nullptr,
            NV, NV, CV, sQK, sQK, sAttn);
    }
    // 5) softmax stats + normalize/transpose/split
    stats_kernel<<<BATCH * NV, 256>>>(attn, stats);
    {
        dim3 grid(NV / 32, NV / 32, BATCH);
        normt_kernel<<<grid, 256>>>(attn, stats, athi, atlo);
    }
    // 6) GEMM4 swapped: OUTT[n][c_v] = P^T "@" G  (M=2048, N=256, K=2048)
    {
        dim3 grid(CV / 128, NV / 128, BATCH);
        mma_gemm<false, false, true><<<grid, 256, MM_SMEM>>>(
            athi, atlo, ghi, glo, nullptr, nullptr,
            nullptr, othi, otlo, NV, CV, NV, sAttn, sProj, sQK);
    }
    // 7) de-interleave OUTT -> outT [hw][ic]
    deint_kernel<<<4096, 256>>>(othi, otlo, obhi, oblo);
    // 8) mask (tensor, bias+residual): M=256, N=4096, K=128
    {
        dim3 grid(HW / 128, CH / 128, BATCH);
        mma_gemm<true, true, false><<<grid, 256, MM_SMEM>>>(
            wm_hi, wm_lo, obhi, oblo, b_mask, x,
            out, nullptr, nullptr, CH, HW, ICH, 0, sProj, sX);
    }
}